// round 11
// baseline (speedup 1.0000x reference)
#include <cuda_runtime.h>

#define LSEQ 512
#define BSZ 1024
#define NTAG 64
#define START_TAG 62
#define END_TAG 63

typedef unsigned long long ull;

// ---- packed f32x2 helpers (Blackwell FFMA2: only reachable via PTX) ----
__device__ __forceinline__ ull pack2(float lo, float hi) {
    ull d;
    asm("mov.b64 %0, {%1, %2};" : "=l"(d) : "f"(lo), "f"(hi));
    return d;
}
__device__ __forceinline__ void unpack2(ull v, float& lo, float& hi) {
    asm("mov.b64 {%0, %1}, %2;" : "=f"(lo), "=f"(hi) : "l"(v));
}
__device__ __forceinline__ ull fma2(ull a, ull b, ull c) {
    ull d;
    asm("fma.rn.f32x2 %0, %1, %2, %3;" : "=l"(d) : "l"(a), "l"(b), "l"(c));
    return d;
}

// ============================================================================
// Fused CRF kernel: 4 OUTPUTS x HALF-K PER THREAD (the register-reuse round).
//
// Diagnosis from rounds 1-10: the invariant wall is v-bytes-per-thread x
// threads-per-batch (every thread read all 256B of v to make 1-2 outputs).
// Here a warp owns ONE batch; lane (half=lane>>4, hl=lane&15) computes
// output tags 4hl..4hl+3 over the input half [32*half, 32*half+32):
//   - E: 4 outs x 16 k-pairs = 64 f32x2 regs (128 regs -- fits)
//   - v-read: 128B = 8 LDS.128 per thread (4x less traffic per batch)
//   - 64 FFMA2 (4 chains depth 16), K-halves merged by 4 shfl_xor(16)
//   - both halves hold identical new v: half0 stores copy A, half1 copy B
//     (copy B base shifted 4 words so half-split broadcast reads hit
//     disjoint banks), 1 STS.128 each
// No block barriers: warps are independent (__syncwarp only). 128-thread
// blocks put warps on all 4 SMSPs; grid 256 (~6.9 warps/SM).
// Numerics = proven R4 path: linear-domain v' = (E@v)*exp(feat); renorm
// every 4 steps, deferred (butterfly max at l%4==3, consumed as 1/hi folded
// into exp(feat) + c += log(hi) at next l%4==0; no pending obligation at
// exit). feats: LDG.128 (4 contiguous tags), 2-deep ring.
// Realpath fused as a per-warp tail.
// ============================================================================
__global__ void __launch_bounds__(128, 2) crf_fused_kernel(
    const float* __restrict__ feats,
    const int*   __restrict__ tags,
    const float* __restrict__ mask,
    const float* __restrict__ transition,
    float* __restrict__ out)
{
    // per-warp: [pingpong][136]: copy A = [0..63], copy B = [68..131]
    __shared__ __align__(16) float vsh[4][2][136];

    const int lane = threadIdx.x & 31;
    const int wib  = threadIdx.x >> 5;
    const int b    = blockIdx.x * 4 + wib;   // one batch per warp
    const int half = lane >> 4;              // K-half owned
    const int hl   = lane & 15;              // output group
    const int tb   = 4 * hl;                 // first of 4 owned tags
    const int kb   = 32 * half;              // input base

    // E2[o][j] = ( E[tb+o, kb+2j], E[tb+o, kb+2j+1] ),  64 ull = 128 regs
    ull E2[4][16];
#pragma unroll
    for (int o = 0; o < 4; ++o)
#pragma unroll
        for (int j = 0; j < 16; ++j)
            E2[o][j] = pack2(
                __expf(__ldg(transition + (tb + o) * NTAG + kb + 2 * j)),
                __expf(__ldg(transition + (tb + o) * NTAG + kb + 2 * j + 1)));

    // v0 = one-hot(START); both copies written (half0 -> A, half1 -> B)
    float myv[4];
#pragma unroll
    for (int o = 0; o < 4; ++o) myv[o] = (tb + o == START_TAG) ? 1.0f : 0.0f;
    {
        float* dst = vsh[wib][0] + (half ? 68 : 0) + tb;
        *(float4*)dst = make_float4(myv[0], myv[1], myv[2], myv[3]);
    }
    float c = 0.0f;
    float maxv = 1.0f;   // pending renorm factor (first consume is no-op)
    __syncwarp();

    // 2-deep prefetch ring: feat quad (LDG.128) + warp-uniform mask
    const float* fptr = feats + (size_t)b * NTAG + tb;
    float4 fr[2];
    float  mr[2];
#pragma unroll
    for (int u = 0; u < 2; ++u) {
        fr[u] = *(const float4*)(fptr + (size_t)u * (BSZ * NTAG));
        mr[u] = __ldg(mask + u * BSZ + b);
    }

    for (int l4 = 0; l4 < LSEQ; l4 += 4) {
#pragma unroll
        for (int u = 0; u < 4; ++u) {
            const int l = l4 + u;
            const float4 f = fr[l & 1];
            const float  m = mr[l & 1];
            int ln = l + 2;
            if (ln > LSEQ - 1) ln = LSEQ - 1;
            fr[l & 1] = *(const float4*)(fptr + (size_t)ln * (BSZ * NTAG));
            mr[l & 1] = __ldg(mask + ln * BSZ + b);

            // consume deferred renorm (every 4th step)
            float scale = 1.0f;
            if (u == 0) {
                scale = __fdividef(1.0f, maxv);
                c += __logf(maxv);
            }
            float ef[4];
            ef[0] = __expf(f.x) * scale;
            ef[1] = __expf(f.y) * scale;
            ef[2] = __expf(f.z) * scale;
            ef[3] = __expf(f.w) * scale;

            // partial MV over this lane's K-half: 4 chains of depth 16
            // half0 reads copy A [0..31]; half1 reads copy B [100..131]
            const ulonglong2* vp = (const ulonglong2*)
                (vsh[wib][l & 1] + (half ? (68 + 32) : 0));
            ull a0 = 0ull, a1 = 0ull, a2 = 0ull, a3 = 0ull;
#pragma unroll
            for (int j = 0; j < 8; ++j) {
                const ulonglong2 w = vp[j];   // k-pairs 2j, 2j+1
                a0 = fma2(E2[0][2 * j], w.x, a0);
                a1 = fma2(E2[1][2 * j], w.x, a1);
                a2 = fma2(E2[2][2 * j], w.x, a2);
                a3 = fma2(E2[3][2 * j], w.x, a3);
                a0 = fma2(E2[0][2 * j + 1], w.y, a0);
                a1 = fma2(E2[1][2 * j + 1], w.y, a1);
                a2 = fma2(E2[2][2 * j + 1], w.y, a2);
                a3 = fma2(E2[3][2 * j + 1], w.y, a3);
            }
            float p0l, p0h, p1l, p1h, p2l, p2h, p3l, p3h;
            unpack2(a0, p0l, p0h);
            unpack2(a1, p1l, p1h);
            unpack2(a2, p2l, p2h);
            unpack2(a3, p3l, p3h);
            float o0 = p0l + p0h, o1 = p1l + p1h;
            float o2 = p2l + p2h, o3 = p3l + p3h;

            // merge K-halves: partner lane is lane ^ 16
            o0 += __shfl_xor_sync(0xffffffffu, o0, 16);
            o1 += __shfl_xor_sync(0xffffffffu, o1, 16);
            o2 += __shfl_xor_sync(0xffffffffu, o2, 16);
            o3 += __shfl_xor_sync(0xffffffffu, o3, 16);

            float n0 = o0 * ef[0], n1 = o1 * ef[1];
            float n2 = o2 * ef[2], n3 = o3 * ef[3];
            if (m == 0.0f) {   // masked step keeps old v (scale still applies)
                n0 = myv[0] * scale; n1 = myv[1] * scale;
                n2 = myv[2] * scale; n3 = myv[3] * scale;
            }
            myv[0] = n0; myv[1] = n1; myv[2] = n2; myv[3] = n3;

            // dual-copy store: half0 -> copy A, half1 -> copy B
            {
                float* dst = vsh[wib][(l & 1) ^ 1] + (half ? 68 : 0) + tb;
                *(float4*)dst = make_float4(n0, n1, n2, n3);
            }

            if (u == 3) {   // produce next renorm factor (16-group butterfly)
                float hi = fmaxf(fmaxf(n0, n1), fmaxf(n2, n3));
                hi = fmaxf(hi, __shfl_xor_sync(0xffffffffu, hi, 1));
                hi = fmaxf(hi, __shfl_xor_sync(0xffffffffu, hi, 2));
                hi = fmaxf(hi, __shfl_xor_sync(0xffffffffu, hi, 4));
                hi = fmaxf(hi, __shfl_xor_sync(0xffffffffu, hi, 8));
                maxv = hi;
            }
            __syncwarp();
        }
    }

    // allpath = c + log( sum_t v[t]*exp(T[END,t]) ); 16-group holds all tags
    float s = myv[0] * __expf(__ldg(transition + END_TAG * NTAG + tb))
            + myv[1] * __expf(__ldg(transition + END_TAG * NTAG + tb + 1))
            + myv[2] * __expf(__ldg(transition + END_TAG * NTAG + tb + 2))
            + myv[3] * __expf(__ldg(transition + END_TAG * NTAG + tb + 3));
    s += __shfl_xor_sync(0xffffffffu, s, 1);
    s += __shfl_xor_sync(0xffffffffu, s, 2);
    s += __shfl_xor_sync(0xffffffffu, s, 4);
    s += __shfl_xor_sync(0xffffffffu, s, 8);
    const float allpath = c + __logf(s);

    // ---- realpath tail: lanes split L (16 each), independent gathers ----
    float rsum = 0.0f, rlen = 0.0f;
#pragma unroll
    for (int i = 0; i < 16; ++i) {
        const int l = lane + 32 * i;
        int tag  = __ldg(tags + l * BSZ + b);
        int prev = (l == 0) ? START_TAG : __ldg(tags + (l - 1) * BSZ + b);
        float m  = __ldg(mask + l * BSZ + b);
        float emit = __ldg(feats + ((size_t)l * BSZ + b) * NTAG + tag);
        float tr   = __ldg(transition + tag * NTAG + prev);
        rsum += (emit + tr) * m;
        rlen += m;
    }
#pragma unroll
    for (int o = 16; o > 0; o >>= 1) {
        rsum += __shfl_xor_sync(0xffffffffu, rsum, o);
        rlen += __shfl_xor_sync(0xffffffffu, rlen, o);
    }
    if (lane == 0) {
        const int length = (int)(rlen + 0.5f);
        const int last = (length > 0) ? __ldg(tags + (length - 1) * BSZ + b)
                                      : START_TAG;
        const float real = rsum + __ldg(transition + END_TAG * NTAG + last);
        out[b] = allpath - real;
    }
}

extern "C" void kernel_launch(void* const* d_in, const int* in_sizes, int n_in,
                              void* d_out, int out_size) {
    const float* feats      = (const float*)d_in[0];
    const int*   tags       = (const int*)  d_in[1];
    const float* mask       = (const float*)d_in[2];
    const float* transition = (const float*)d_in[3];
    float* out = (float*)d_out;

    crf_fused_kernel<<<BSZ / 4, 128>>>(feats, tags, mask, transition, out);
}

// round 12
// speedup vs baseline: 1.0367x; 1.0367x over previous
#include <cuda_runtime.h>

#define LSEQ 512
#define BSZ 1024
#define NTAG 64
#define START_TAG 62
#define END_TAG 63

typedef unsigned long long ull;

// ---- packed f32x2 helpers (Blackwell FFMA2: only reachable via PTX) ----
__device__ __forceinline__ ull pack2(float lo, float hi) {
    ull d;
    asm("mov.b64 %0, {%1, %2};" : "=l"(d) : "f"(lo), "f"(hi));
    return d;
}
__device__ __forceinline__ void unpack2(ull v, float& lo, float& hi) {
    asm("mov.b64 {%0, %1}, %2;" : "=f"(lo), "=f"(hi) : "l"(v));
}
__device__ __forceinline__ ull fma2(ull a, ull b, ull c) {
    ull d;
    asm("fma.rn.f32x2 %0, %1, %2, %3;" : "=l"(d) : "l"(a), "l"(b), "l"(c));
    return d;
}

// ============================================================================
// Fused CRF kernel: FOUR WARPS PER BATCH (K-quarter split) -- the occupancy
// round. Evidence from R1-R11: per-step time is latency-exposure bound; the
// only lever that ever moved the needle was warps/SMSP. This doubles it
// again: 1024 blocks x 128 threads = 4096 warps (~6.9/SMSP, ~40% occ).
//
// Block = 1 batch. Warp q owns inputs [16q, 16q+16). Thread owns output
// pair (t0,t1) = (2*lane, 2*lane+1):
//   E2[o][j] = (E[t_o, kb+2j], E[t_o, kb+2j+1]) -- 16 f32x2 = 32 regs only.
//   Per step: 4 broadcast LDS.128 (quarter of v) + 16 FFMA2 (2 chains x8)
//   -> STS.64 partial -> bar -> 4x LDS.64 partial-sum (every warp redundantly
//   reconstructs the FULL new v for its pair: renorm stays intra-warp and
//   the mask-keep path has the old value locally) -> warp 0 stores v -> bar.
// Numerics = proven path: linear-domain v' = (E@v)*exp(feat)*scale; renorm
// every 4 steps, deferred (butterfly max at u==3 into a register -- all
// warps compute it identically; consumed at next u==0 as scale=1/hi with
// c += log(hi); first consume is a no-op; no pending obligation at exit).
// Realpath fused: 128 threads split L (4 each).
// ============================================================================
__global__ void __launch_bounds__(128, 7) crf_fused_kernel(
    const float* __restrict__ feats,
    const int*   __restrict__ tags,
    const float* __restrict__ mask,
    const float* __restrict__ transition,
    float* __restrict__ out)
{
    __shared__ __align__(16) float  vbuf[2][NTAG];   // ping-pong v
    __shared__ __align__(16) float2 pbuf[4][32];     // per-warp partials
    __shared__ float redsh[9];  // [0]=allpath  [1..4]=rsum/warp [5..8]=rlen

    const int tid  = threadIdx.x;
    const int w    = tid >> 5;        // K-quarter owned by this warp
    const int lane = tid & 31;
    const int b    = blockIdx.x;
    const int t0   = 2 * lane;        // output pair owned by this thread
    const int t1   = t0 + 1;
    const int kb   = 16 * w;          // input base

    // E2[o][j] = ( exp(T[t_o, kb+2j]), exp(T[t_o, kb+2j+1]) ) -- 32 regs
    ull E2[2][8];
#pragma unroll
    for (int j = 0; j < 8; ++j) {
        E2[0][j] = pack2(__expf(__ldg(transition + t0 * NTAG + kb + 2 * j)),
                         __expf(__ldg(transition + t0 * NTAG + kb + 2 * j + 1)));
        E2[1][j] = pack2(__expf(__ldg(transition + t1 * NTAG + kb + 2 * j)),
                         __expf(__ldg(transition + t1 * NTAG + kb + 2 * j + 1)));
    }

    // v0 = one-hot(START); c = 0; first renorm-consume is a no-op
    float myv0 = (t0 == START_TAG) ? 1.0f : 0.0f;
    float myv1 = (t1 == START_TAG) ? 1.0f : 0.0f;
    if (w == 0) ((float2*)vbuf[0])[lane] = make_float2(myv0, myv1);
    float c = 0.0f;
    float maxv = 1.0f;
    __syncthreads();

    // 2-deep prefetch ring: feat pair (LDG.64) + block-uniform mask
    const float* fptr = feats + (size_t)b * NTAG + t0;
    float2 fr[2];
    float  mr[2];
#pragma unroll
    for (int u = 0; u < 2; ++u) {
        fr[u] = *(const float2*)(fptr + (size_t)u * (BSZ * NTAG));
        mr[u] = __ldg(mask + u * BSZ + b);
    }

    for (int l4 = 0; l4 < LSEQ; l4 += 4) {
#pragma unroll
        for (int u = 0; u < 4; ++u) {
            const int l = l4 + u;
            const float2 f = fr[l & 1];
            const float  m = mr[l & 1];
            int ln = l + 2;
            if (ln > LSEQ - 1) ln = LSEQ - 1;
            fr[l & 1] = *(const float2*)(fptr + (size_t)ln * (BSZ * NTAG));
            mr[l & 1] = __ldg(mask + ln * BSZ + b);

            // consume deferred renorm (every 4th step)
            float scale = 1.0f;
            if (u == 0) {
                scale = __fdividef(1.0f, maxv);
                c += __logf(maxv);
            }
            const float ef0 = __expf(f.x) * scale;
            const float ef1 = __expf(f.y) * scale;

            // partial MV over this warp's K-quarter: 4 uniform LDS.128,
            // 16 FFMA2 in 2 chains of depth 8
            const ulonglong2* vp = (const ulonglong2*)(vbuf[l & 1] + kb);
            ull a0 = 0ull, a1 = 0ull;
#pragma unroll
            for (int j = 0; j < 4; ++j) {
                const ulonglong2 w2 = vp[j];   // input pairs 2j*2, 2j*2+1
                a0 = fma2(E2[0][2 * j],     w2.x, a0);
                a1 = fma2(E2[1][2 * j],     w2.x, a1);
                a0 = fma2(E2[0][2 * j + 1], w2.y, a0);
                a1 = fma2(E2[1][2 * j + 1], w2.y, a1);
            }
            float p0l, p0h, p1l, p1h;
            unpack2(a0, p0l, p0h);
            unpack2(a1, p1l, p1h);

            // exchange partials across the 4 K-quarters
            pbuf[w][lane] = make_float2(p0l + p0h, p1l + p1h);
            __syncthreads();
            const float2 q0 = pbuf[0][lane];
            const float2 q1 = pbuf[1][lane];
            const float2 q2 = pbuf[2][lane];
            const float2 q3 = pbuf[3][lane];

            float n0 = ((q0.x + q1.x) + (q2.x + q3.x)) * ef0;
            float n1 = ((q0.y + q1.y) + (q2.y + q3.y)) * ef1;
            if (m == 0.0f) { n0 = myv0 * scale; n1 = myv1 * scale; }
            myv0 = n0;
            myv1 = n1;

            if (w == 0)   // one copy of the new v, read as broadcasts next step
                ((float2*)vbuf[(l & 1) ^ 1])[lane] = make_float2(n0, n1);

            if (u == 3) {   // produce next renorm factor (all warps identical)
                float hi = fmaxf(n0, n1);
#pragma unroll
                for (int o = 16; o > 0; o >>= 1)
                    hi = fmaxf(hi, __shfl_xor_sync(0xffffffffu, hi, o));
                maxv = hi;
            }
            __syncthreads();
        }
    }

    // allpath = c + log( sum_t v[t] * exp(T[END,t]) ); warp 0 has the pairs
    if (w == 0) {
        float s = myv0 * __expf(__ldg(transition + END_TAG * NTAG + t0))
                + myv1 * __expf(__ldg(transition + END_TAG * NTAG + t1));
#pragma unroll
        for (int o = 16; o > 0; o >>= 1)
            s += __shfl_xor_sync(0xffffffffu, s, o);
        if (lane == 0) redsh[0] = c + __logf(s);
    }

    // ---- realpath tail: 128 threads split L (4 each) ----
    float rsum = 0.0f, rlen = 0.0f;
#pragma unroll
    for (int i = 0; i < 4; ++i) {
        const int l = tid + 128 * i;
        int tag  = __ldg(tags + l * BSZ + b);
        int prev = (l == 0) ? START_TAG : __ldg(tags + (l - 1) * BSZ + b);
        float m  = __ldg(mask + l * BSZ + b);
        float emit = __ldg(feats + ((size_t)l * BSZ + b) * NTAG + tag);
        float tr   = __ldg(transition + tag * NTAG + prev);
        rsum += (emit + tr) * m;
        rlen += m;
    }
#pragma unroll
    for (int o = 16; o > 0; o >>= 1) {
        rsum += __shfl_xor_sync(0xffffffffu, rsum, o);
        rlen += __shfl_xor_sync(0xffffffffu, rlen, o);
    }
    if (lane == 0) { redsh[1 + w] = rsum; redsh[5 + w] = rlen; }
    __syncthreads();

    if (tid == 0) {
        const float rs = (redsh[1] + redsh[2]) + (redsh[3] + redsh[4]);
        const float lt = (redsh[5] + redsh[6]) + (redsh[7] + redsh[8]);
        const int length = (int)(lt + 0.5f);
        const int last = (length > 0) ? __ldg(tags + (length - 1) * BSZ + b)
                                      : START_TAG;
        const float real = rs + __ldg(transition + END_TAG * NTAG + last);
        out[b] = redsh[0] - real;
    }
}

extern "C" void kernel_launch(void* const* d_in, const int* in_sizes, int n_in,
                              void* d_out, int out_size) {
    const float* feats      = (const float*)d_in[0];
    const int*   tags       = (const int*)  d_in[1];
    const float* mask       = (const float*)d_in[2];
    const float* transition = (const float*)d_in[3];
    float* out = (float*)d_out;

    crf_fused_kernel<<<BSZ, 128>>>(feats, tags, mask, transition, out);
}